// round 16
// baseline (speedup 1.0000x reference)
#include <cuda_runtime.h>
#include <cuda_fp16.h>
#include <cstdint>

#define DIM 1024
#define NH 16
#define HD 64
#define TSEQ 2048
#define BT 4096          // B * T
#define HGS 24           // fp16 gemm smem stride (halfs): 12r mod 32 distinct -> conflict-free
#define HSTR 72          // attention smem stride (halfs)
#define QT 128           // attention query-tile rows

// Scratch (static device arrays; allocation in kernel_launch is forbidden)
__device__ float  g_h[BT * DIM];
__device__ __half g_q[BT * DIM];
__device__ __half g_k[BT * DIM];
__device__ __half g_v[BT * DIM];
__device__ float  g_att[BT * DIM];

// ---------------------------------------------------------------------------
// LayerNorm: one block per row of x [4096, 1024]
// ---------------------------------------------------------------------------
__global__ void ln_kernel(const float* __restrict__ x,
                          const float* __restrict__ gamma,
                          const float* __restrict__ beta,
                          float* __restrict__ out) {
    int row = blockIdx.x;
    const float* xr = x + (size_t)row * DIM;
    float* orow = out + (size_t)row * DIM;
    int t = threadIdx.x;

    float v[4];
    float sum = 0.f, sq = 0.f;
#pragma unroll
    for (int i = 0; i < 4; i++) {
        float val = xr[t + i * 256];
        v[i] = val;
        sum += val;
        sq += val * val;
    }
#pragma unroll
    for (int o = 16; o > 0; o >>= 1) {
        sum += __shfl_xor_sync(0xffffffffu, sum, o);
        sq  += __shfl_xor_sync(0xffffffffu, sq, o);
    }
    __shared__ float s1[8], s2[8];
    if ((t & 31) == 0) { s1[t >> 5] = sum; s2[t >> 5] = sq; }
    __syncthreads();
    float tot = 0.f, totq = 0.f;
#pragma unroll
    for (int i = 0; i < 8; i++) { tot += s1[i]; totq += s2[i]; }
    float mu   = tot * (1.0f / DIM);
    float var  = totq * (1.0f / DIM) - mu * mu;
    float rstd = rsqrtf(var + 1e-5f);
#pragma unroll
    for (int i = 0; i < 4; i++) {
        int c = t + i * 256;
        orow[c] = (v[i] - mu) * rstd * gamma[c] + beta[c];
    }
}

// ---------------------------------------------------------------------------
// helpers
// ---------------------------------------------------------------------------
__device__ __forceinline__ uint32_t pack_h2(float a, float b) {
    __half2 h = __floats2half2_rn(a, b);
    return *reinterpret_cast<uint32_t*>(&h);
}

__device__ __forceinline__ void mma_f16(float* c, const uint32_t* a,
                                        const uint32_t* b) {
    asm volatile(
        "mma.sync.aligned.m16n8k16.row.col.f32.f16.f16.f32 "
        "{%0,%1,%2,%3}, {%4,%5,%6,%7}, {%8,%9}, {%0,%1,%2,%3};\n"
        : "+f"(c[0]), "+f"(c[1]), "+f"(c[2]), "+f"(c[3])
        : "r"(a[0]), "r"(a[1]), "r"(a[2]), "r"(a[3]), "r"(b[0]), "r"(b[1]));
}

__device__ __forceinline__ void ldsm_x4(uint32_t& r0, uint32_t& r1,
                                        uint32_t& r2, uint32_t& r3,
                                        uint32_t addr) {
    asm volatile(
        "ldmatrix.sync.aligned.m8n8.x4.shared.b16 {%0,%1,%2,%3}, [%4];"
        : "=r"(r0), "=r"(r1), "=r"(r2), "=r"(r3) : "r"(addr));
}

__device__ __forceinline__ void ldsm_x4_t(uint32_t& r0, uint32_t& r1,
                                          uint32_t& r2, uint32_t& r3,
                                          uint32_t addr) {
    asm volatile(
        "ldmatrix.sync.aligned.m8n8.x4.trans.shared.b16 {%0,%1,%2,%3}, [%4];"
        : "=r"(r0), "=r"(r1), "=r"(r2), "=r"(r3) : "r"(addr));
}

__device__ __forceinline__ void store_pair(float* C, size_t idx, float x, float y) {
    float2 v; v.x = x; v.y = y;
    *(float2*)&C[idx] = v;
}
__device__ __forceinline__ void store_pair(__half* C, size_t idx, float x, float y) {
    *(__half2*)&C[idx] = __floats2half2_rn(x, y);
}

__device__ __forceinline__ uint4 cvt8_f2h(const float4& a, const float4& b) {
    uint4 u;
    u.x = pack_h2(a.x, a.y); u.y = pack_h2(a.z, a.w);
    u.z = pack_h2(b.x, b.y); u.w = pack_h2(b.z, b.w);
    return u;
}

// ---------------------------------------------------------------------------
// fp16 GEMM NT: C[m][n] = sum_k A[m][k]*B[n][k] + bias[n]. fp32 in/acc,
// fp16 mma m16n8k16. 128x128 block, 256 threads = 8 warps (2m x 4n),
// warp tile 64x32, BK=16, 2-stage double buffer, ldmatrix fragment loads.
// Loader: row = tid&127, col-half = (tid>>7)*8 floats (sector-aligned LDG,
// conflict-free uint4 STS with 48-byte row stride).
// ---------------------------------------------------------------------------
template <typename OUT>
__device__ __forceinline__ void gemm_f16_body(const float* __restrict__ A,
                                              const float* __restrict__ B,
                                              const float* __restrict__ bias,
                                              OUT* __restrict__ C,
                                              int M, int N, int K) {
    __shared__ __half As[2][128 * HGS];
    __shared__ __half Bs[2][128 * HGS];

    int tid = threadIdx.x;
    int bm = blockIdx.y * 128;
    int bn = blockIdx.x * 128;
    int w = tid >> 5, lane = tid & 31;
    int wm = (w & 1) * 64;
    int wn = (w >> 1) * 32;
    int lq = lane >> 2;
    int lrm = lane & 3;

    int lrow = tid & 127;          // smem/gmem row
    int lcf  = (tid >> 7) * 8;     // float/half column offset (0 or 8)

    const float* Ap = A + (size_t)(bm + lrow) * K + lcf;
    const float* Bp = B + (size_t)(bn + lrow) * K + lcf;

    int g = lane >> 3;
    int lr8 = lane & 7;
    uint32_t aBase = (uint32_t)__cvta_generic_to_shared(&As[0][0]);
    uint32_t bBase = (uint32_t)__cvta_generic_to_shared(&Bs[0][0]);
    const uint32_t stageBytes = 128 * HGS * 2;
    // A-frag: g&1 -> +8 rows, g>>1 -> +8 k-halfs (validated mapping)
    uint32_t aOff = ((uint32_t)(wm + (g & 1) * 8 + lr8) * HGS + (g >> 1) * 8) * 2;
    // B-frag: g>>1 -> +8 n-rows, g&1 -> +8 k-halfs (validated mapping)
    uint32_t bOff = ((uint32_t)(wn + (g >> 1) * 8 + lr8) * HGS + (g & 1) * 8) * 2;

    float acc[4][4][4];
#pragma unroll
    for (int mi = 0; mi < 4; mi++)
#pragma unroll
        for (int ni = 0; ni < 4; ni++)
#pragma unroll
            for (int r = 0; r < 4; r++) acc[mi][ni][r] = 0.f;

    // Prologue: stage 0
    {
        float4 a0 = *(const float4*)(Ap);
        float4 a1 = *(const float4*)(Ap + 4);
        float4 b0 = *(const float4*)(Bp);
        float4 b1 = *(const float4*)(Bp + 4);
        *(uint4*)&As[0][lrow * HGS + lcf] = cvt8_f2h(a0, a1);
        *(uint4*)&Bs[0][lrow * HGS + lcf] = cvt8_f2h(b0, b1);
    }
    __syncthreads();

    int stage = 0;
    for (int k0 = 0; k0 < K; k0 += 16) {
        int nxt = stage ^ 1;
        bool has_next = (k0 + 16) < K;

        float4 a0, a1, b0, b1;
        if (has_next) {
            a0 = *(const float4*)(Ap + k0 + 16);
            a1 = *(const float4*)(Ap + k0 + 20);
            b0 = *(const float4*)(Bp + k0 + 16);
            b1 = *(const float4*)(Bp + k0 + 20);
        }

        uint32_t aS = aBase + stage * stageBytes + aOff;
        uint32_t bS = bBase + stage * stageBytes + bOff;
        {
            uint32_t af[4][4];
#pragma unroll
            for (int mi = 0; mi < 4; mi++)
                ldsm_x4(af[mi][0], af[mi][1], af[mi][2], af[mi][3],
                        aS + (uint32_t)(mi * 16 * HGS) * 2);
            uint32_t bf[4][2];
#pragma unroll
            for (int np = 0; np < 2; np++) {
                uint32_t r0, r1, r2, r3;
                ldsm_x4(r0, r1, r2, r3, bS + (uint32_t)(np * 16 * HGS) * 2);
                bf[2 * np][0] = r0; bf[2 * np][1] = r1;
                bf[2 * np + 1][0] = r2; bf[2 * np + 1][1] = r3;
            }
#pragma unroll
            for (int mi = 0; mi < 4; mi++)
#pragma unroll
                for (int ni = 0; ni < 4; ni++)
                    mma_f16(acc[mi][ni], af[mi], bf[ni]);
        }

        if (has_next) {
            *(uint4*)&As[nxt][lrow * HGS + lcf] = cvt8_f2h(a0, a1);
            *(uint4*)&Bs[nxt][lrow * HGS + lcf] = cvt8_f2h(b0, b1);
            __syncthreads();
        }
        stage = nxt;
    }

#pragma unroll
    for (int mi = 0; mi < 4; mi++) {
#pragma unroll
        for (int ni = 0; ni < 4; ni++) {
            int row0 = bm + wm + mi * 16 + lq;
            int col  = bn + wn + ni * 8 + lrm * 2;
            float2 bb = *(const float2*)&bias[col];
            store_pair(C, (size_t)row0 * N + col,
                       acc[mi][ni][0] + bb.x, acc[mi][ni][1] + bb.y);
            store_pair(C, (size_t)(row0 + 8) * N + col,
                       acc[mi][ni][2] + bb.x, acc[mi][ni][3] + bb.y);
        }
    }
}

__global__ __launch_bounds__(256) void gemm_f16(const float* __restrict__ A,
                                                const float* __restrict__ B,
                                                const float* __restrict__ bias,
                                                float* __restrict__ C,
                                                int M, int N, int K) {
    gemm_f16_body<float>(A, B, bias, C, M, N, K);
}

// Fused QKV GEMM with fp16 outputs for the attention kernel
__global__ __launch_bounds__(256) void gemm_qkv(const float* __restrict__ A,
                                                const float* __restrict__ Wq,
                                                const float* __restrict__ bq,
                                                __half* __restrict__ Oq,
                                                const float* __restrict__ Wk,
                                                const float* __restrict__ bk,
                                                __half* __restrict__ Ok,
                                                const float* __restrict__ Wv,
                                                const float* __restrict__ bv,
                                                __half* __restrict__ Ov,
                                                int M, int N, int K) {
    int z = blockIdx.z;
    const float* W = (z == 0) ? Wq : (z == 1) ? Wk : Wv;
    const float* b = (z == 0) ? bq : (z == 1) ? bk : bv;
    __half* O      = (z == 0) ? Oq : (z == 1) ? Ok : Ov;
    gemm_f16_body<__half>(A, W, b, O, M, N, K);
}

// ---------------------------------------------------------------------------
// fp16 tensor-core causal flash attention (FA2-style), 128-row Q tile.
// (frozen from R12)
// ---------------------------------------------------------------------------
__global__ __launch_bounds__(256) void attn_kernel(const __half* __restrict__ Q,
                                                   const __half* __restrict__ K,
                                                   const __half* __restrict__ V,
                                                   float* __restrict__ O) {
    __shared__ __half sQ[QT * HSTR];
    __shared__ __half sK[64 * HSTR];
    __shared__ __half sV[64 * HSTR];

    int tid = threadIdx.x;
    int w = tid >> 5, lane = tid & 31;
    int lq = lane >> 2, lrm = lane & 3;
    int rowA = w * 16;
    int qblk = blockIdx.x;
    int h = blockIdx.y;
    int b = blockIdx.z;
    int q0 = qblk * QT;
    size_t base = ((size_t)b * TSEQ) * DIM + h * HD;

    int qlr = tid >> 1;
    int qlc = (tid & 1) * 32;
    int klr = tid & 63;
    int klc = (tid >> 6) * 16;

    int g = lane >> 3;
    int lr8 = lane & 7;
    uint32_t qBase = (uint32_t)__cvta_generic_to_shared(sQ);
    uint32_t kBase = (uint32_t)__cvta_generic_to_shared(sK);
    uint32_t vBase = (uint32_t)__cvta_generic_to_shared(sV);
    uint32_t aOff = ((uint32_t)((rowA + (g & 1) * 8 + lr8) * HSTR) + (g >> 1) * 8) * 2;
    uint32_t kOff = ((uint32_t)(((g >> 1) * 8 + lr8) * HSTR) + (g & 1) * 8) * 2;
    uint32_t vOff = ((uint32_t)(((g & 1) * 8 + lr8) * HSTR) + (g >> 1) * 8) * 2;

    {
        const uint4* src = (const uint4*)(Q + base + (size_t)(q0 + qlr) * DIM + qlc);
        uint4* dst = (uint4*)(sQ + qlr * HSTR + qlc);
#pragma unroll
        for (int i = 0; i < 4; i++) dst[i] = src[i];
    }

    float o_frag[8][4];
#pragma unroll
    for (int n = 0; n < 8; n++)
#pragma unroll
        for (int r = 0; r < 4; r++) o_frag[n][r] = 0.f;
    float m0 = -1e30f, m1 = -1e30f, l0 = 0.f, l1 = 0.f;

    int kb_max = 2 * qblk + 1;
    for (int kb = 0; kb <= kb_max; kb++) {
        __syncthreads();
        {
            const uint4* ks = (const uint4*)(K + base + (size_t)(kb * 64 + klr) * DIM + klc);
            const uint4* vs = (const uint4*)(V + base + (size_t)(kb * 64 + klr) * DIM + klc);
            uint4* kd = (uint4*)(sK + klr * HSTR + klc);
            uint4* vd = (uint4*)(sV + klr * HSTR + klc);
            kd[0] = ks[0]; kd[1] = ks[1];
            vd[0] = vs[0]; vd[1] = vs[1];
        }
        __syncthreads();

        if (kb * 64 > q0 + rowA + 15) continue;   // fully masked, warp-uniform

        float s_frag[8][4];
#pragma unroll
        for (int n = 0; n < 8; n++)
#pragma unroll
            for (int r = 0; r < 4; r++) s_frag[n][r] = 0.f;

#pragma unroll
        for (int kc = 0; kc < 4; kc++) {
            uint32_t af[4];
            ldsm_x4(af[0], af[1], af[2], af[3], qBase + aOff + (uint32_t)(kc * 16) * 2);
            uint32_t bf[8][2];
#pragma unroll
            for (int np = 0; np < 4; np++) {
                uint32_t r0, r1, r2, r3;
                ldsm_x4(r0, r1, r2, r3,
                        kBase + kOff + (uint32_t)(np * 16 * HSTR + kc * 16) * 2);
                bf[2 * np][0] = r0; bf[2 * np][1] = r1;
                bf[2 * np + 1][0] = r2; bf[2 * np + 1][1] = r3;
            }
#pragma unroll
            for (int n = 0; n < 8; n++)
                mma_f16(s_frag[n], af, bf[n]);
        }
#pragma unroll
        for (int n = 0; n < 8; n++)
#pragma unroll
            for (int r = 0; r < 4; r++) s_frag[n][r] *= 0.125f;

        if (kb * 64 + 63 > q0 + rowA) {
            int r0 = q0 + rowA + lq, r1 = q0 + rowA + lq + 8;
            int cbase = kb * 64;
#pragma unroll
            for (int n = 0; n < 8; n++) {
                int c = cbase + 8 * n + 2 * lrm;
                if (c > r0)     s_frag[n][0] = -1e30f;
                if (c + 1 > r0) s_frag[n][1] = -1e30f;
                if (c > r1)     s_frag[n][2] = -1e30f;
                if (c + 1 > r1) s_frag[n][3] = -1e30f;
            }
        }

        {
            float mloc0 = -1e30f, mloc1 = -1e30f;
#pragma unroll
            for (int n = 0; n < 8; n++) {
                mloc0 = fmaxf(mloc0, fmaxf(s_frag[n][0], s_frag[n][1]));
                mloc1 = fmaxf(mloc1, fmaxf(s_frag[n][2], s_frag[n][3]));
            }
            mloc0 = fmaxf(mloc0, __shfl_xor_sync(0xffffffffu, mloc0, 1));
            mloc0 = fmaxf(mloc0, __shfl_xor_sync(0xffffffffu, mloc0, 2));
            mloc1 = fmaxf(mloc1, __shfl_xor_sync(0xffffffffu, mloc1, 1));
            mloc1 = fmaxf(mloc1, __shfl_xor_sync(0xffffffffu, mloc1, 2));
            float mn0 = fmaxf(m0, mloc0), mn1 = fmaxf(m1, mloc1);
            float c0 = __expf(m0 - mn0), c1 = __expf(m1 - mn1);
            float ps0 = 0.f, ps1 = 0.f;
#pragma unroll
            for (int n = 0; n < 8; n++) {
                float p0 = __expf(s_frag[n][0] - mn0);
                float p1 = __expf(s_frag[n][1] - mn0);
                float p2 = __expf(s_frag[n][2] - mn1);
                float p3 = __expf(s_frag[n][3] - mn1);
                s_frag[n][0] = p0; s_frag[n][1] = p1;
                s_frag[n][2] = p2; s_frag[n][3] = p3;
                ps0 += p0 + p1; ps1 += p2 + p3;
            }
            ps0 += __shfl_xor_sync(0xffffffffu, ps0, 1);
            ps0 += __shfl_xor_sync(0xffffffffu, ps0, 2);
            ps1 += __shfl_xor_sync(0xffffffffu, ps1, 1);
            ps1 += __shfl_xor_sync(0xffffffffu, ps1, 2);
            l0 = l0 * c0 + ps0; m0 = mn0;
            l1 = l1 * c1 + ps1; m1 = mn1;
#pragma unroll
            for (int n = 0; n < 8; n++) {
                o_frag[n][0] *= c0; o_frag[n][1] *= c0;
                o_frag[n][2] *= c1; o_frag[n][3] *= c1;
            }
        }

#pragma unroll
        for (int j = 0; j < 4; j++) {
            uint32_t ap[4];
            ap[0] = pack_h2(s_frag[2 * j][0], s_frag[2 * j][1]);
            ap[1] = pack_h2(s_frag[2 * j][2], s_frag[2 * j][3]);
            ap[2] = pack_h2(s_frag[2 * j + 1][0], s_frag[2 * j + 1][1]);
            ap[3] = pack_h2(s_frag[2 * j + 1][2], s_frag[2 * j + 1][3]);
            uint32_t bf[8][2];
#pragma unroll
            for (int np = 0; np < 4; np++) {
                uint32_t r0, r1, r2, r3;
                ldsm_x4_t(r0, r1, r2, r3,
                          vBase + vOff + (uint32_t)(j * 16 * HSTR + np * 16) * 2);
                bf[2 * np][0] = r0; bf[2 * np][1] = r1;
                bf[2 * np + 1][0] = r2; bf[2 * np + 1][1] = r3;
            }
#pragma unroll
            for (int n = 0; n < 8; n++)
                mma_f16(o_frag[n], ap, bf[n]);
        }
    }

    float i0 = 1.0f / l0, i1 = 1.0f / l1;
    float* d0 = O + base + (size_t)(q0 + rowA + lq) * DIM;
    float* d1 = O + base + (size_t)(q0 + rowA + lq + 8) * DIM;
#pragma unroll
    for (int n = 0; n < 8; n++) {
        int col = 8 * n + 2 * lrm;
        float2 w0; w0.x = o_frag[n][0] * i0; w0.y = o_frag[n][1] * i0;
        float2 w1; w1.x = o_frag[n][2] * i1; w1.y = o_frag[n][3] * i1;
        *(float2*)&d0[col] = w0;
        *(float2*)&d1[col] = w1;
    }
}

// ---------------------------------------------------------------------------
extern "C" void kernel_launch(void* const* d_in, const int* in_sizes, int n_in,
                              void* d_out, int out_size) {
    const float* x  = (const float*)d_in[0];
    const float* g1 = (const float*)d_in[1];
    const float* b1 = (const float*)d_in[2];
    const float* Wq = (const float*)d_in[3];
    const float* bq = (const float*)d_in[4];
    const float* Wk = (const float*)d_in[5];
    const float* bk = (const float*)d_in[6];
    const float* Wv = (const float*)d_in[7];
    const float* bv = (const float*)d_in[8];
    const float* Wo = (const float*)d_in[9];
    const float* bo = (const float*)d_in[10];
    float* out = (float*)d_out;

    float *h_p, *a_p;
    __half *q_p, *k_p, *v_p;
    cudaGetSymbolAddress((void**)&h_p, g_h);
    cudaGetSymbolAddress((void**)&q_p, g_q);
    cudaGetSymbolAddress((void**)&k_p, g_k);
    cudaGetSymbolAddress((void**)&v_p, g_v);
    cudaGetSymbolAddress((void**)&a_p, g_att);

    ln_kernel<<<BT, 256>>>(x, g1, b1, h_p);

    dim3 qkv_grid(DIM / 128, BT / 128, 3);
    gemm_qkv<<<qkv_grid, 256>>>(h_p, Wq, bq, q_p, Wk, bk, k_p, Wv, bv, v_p,
                                BT, DIM, DIM);

    attn_kernel<<<dim3(TSEQ / QT, NH, 2), 256>>>(q_p, k_p, v_p, a_p);

    dim3 ggrid(DIM / 128, BT / 128);
    gemm_f16<<<ggrid, 256>>>(a_p, Wo, bo, out, BT, DIM, DIM);
}